// round 12
// baseline (speedup 1.0000x reference)
#include <cuda_runtime.h>
#include <cuda_bf16.h>
#include <math.h>
#include <cstdint>

#define Nn    20000
#define PADN  20096      // 157*128
#define Cc    128
#define Ff    512        // HEADS*NHID
#define Ee    320000
#define ET    340000     // E + N self loops
#define XSTR  640        // (NLAYERS+1)*Cc
#define NCLS  40

// ---------------- scratch (no dynamic allocation allowed) ----------------
__device__ float g_as[Nn * 4];             // a_src per node per head
__device__ float g_ad[Nn * 4];             // a_dst per node per head
__device__ int   g_rowptr[Nn + 1];
__device__ int   g_fill[Nn];
__device__ int   g_cnt[Nn];
__device__ int   g_col[ET];
__device__ __nv_bfloat16 g_WThi[Ff * Cc];  // W^T split hi  [n=512][k=128]
__device__ __nv_bfloat16 g_WTlo[Ff * Cc];  // W^T split lo
__device__ __nv_bfloat16 g_zhi[(size_t)PADN * Ff];  // z split hi [n][h*128+c]
__device__ __nv_bfloat16 g_zlo[(size_t)PADN * Ff];  // z split lo (pad rows stay 0)
__device__ float g_Ws4[Cc * 4];            // fold W@att_src  [k][h]
__device__ float g_Wd4[Cc * 4];            // fold W@att_dst  [k][h]

// ---------------- init ---------------------------------------------------
__global__ void init_kernel(const float* __restrict__ x,
                            float* __restrict__ Xall, float* __restrict__ Yall)
{
    int i = blockIdx.x * blockDim.x + threadIdx.x;
    if (i < Nn * Cc) {
        int n = i >> 7, c = i & 127;
        float v = x[i];
        Xall[(size_t)n * XSTR + c] = v;
        Yall[(size_t)n * XSTR + c] = v;
    }
    if (i < Nn) g_cnt[i] = 0;
}

// ---------------- one-time W transpose + bf16 split ----------------------
__global__ void split_w_kernel(const float* __restrict__ W)
{
    int i = blockIdx.x * blockDim.x + threadIdx.x;
    if (i < Cc * Ff) {
        int k = i >> 9, n = i & 511;
        float w = W[i];
        __nv_bfloat16 hi = __float2bfloat16(w);
        __nv_bfloat16 lo = __float2bfloat16(w - __bfloat162float(hi));
        g_WThi[n * Cc + k] = hi;
        g_WTlo[n * Cc + k] = lo;
    }
}

// ---------------- one-time fold: Ws4[k][h] = sum_c W[k,h*128+c]*att_s[h,c]
__global__ void prep_att_kernel(const float* __restrict__ W,
                                const float* __restrict__ att_s,
                                const float* __restrict__ att_d)
{
    int tid = threadIdx.x;          // 512 threads
    int k = tid >> 2, h = tid & 3;
    float s = 0.f, d = 0.f;
    #pragma unroll 4
    for (int c = 0; c < 128; c++) {
        float w = W[(size_t)k * Ff + h * 128 + c];
        s = fmaf(w, att_s[h * 128 + c], s);
        d = fmaf(w, att_d[h * 128 + c], d);
    }
    g_Ws4[k * 4 + h] = s;
    g_Wd4[k * 4 + h] = d;
}

// ---------------- CSR build (by dst, self-loops appended) ----------------
__global__ void count_kernel(const int* __restrict__ dst)
{
    int i = blockIdx.x * blockDim.x + threadIdx.x;
    if (i < ET) {
        int d = (i < Ee) ? dst[i] : (i - Ee);
        atomicAdd(&g_cnt[d], 1);
    }
}

__global__ void scan_kernel()
{
    __shared__ int wsum[32];
    const int t = threadIdx.x, lane = t & 31, wp = t >> 5;
    const int base = t * 20;
    int v[20];
    #pragma unroll
    for (int i = 0; i < 20; i++) {
        int idx = base + i;
        v[i] = (idx < Nn) ? g_cnt[idx] : 0;
    }
    int sum = 0;
    #pragma unroll
    for (int i = 0; i < 20; i++) sum += v[i];
    int x = sum;
    #pragma unroll
    for (int o = 1; o < 32; o <<= 1) {
        int u = __shfl_up_sync(0xffffffffu, x, o);
        if (lane >= o) x += u;
    }
    if (lane == 31) wsum[wp] = x;
    __syncthreads();
    if (wp == 0) {
        int y = wsum[lane];
        #pragma unroll
        for (int o = 1; o < 32; o <<= 1) {
            int u = __shfl_up_sync(0xffffffffu, y, o);
            if (lane >= o) y += u;
        }
        wsum[lane] = y;
    }
    __syncthreads();
    int run = x - sum + (wp ? wsum[wp - 1] : 0);
    #pragma unroll
    for (int i = 0; i < 20; i++) {
        int idx = base + i;
        if (idx < Nn) {
            g_fill[idx] = run;
            run += v[i];
            g_rowptr[idx + 1] = run;
        }
    }
    if (t == 0) g_rowptr[0] = 0;
}

__global__ void fill_kernel(const int* __restrict__ src, const int* __restrict__ dst)
{
    int i = blockIdx.x * blockDim.x + threadIdx.x;
    if (i < ET) {
        int s, d;
        if (i < Ee) { s = src[i]; d = dst[i]; }
        else        { s = d = i - Ee; }
        int p = atomicAdd(&g_fill[d], 1);
        g_col[p] = s;
    }
}

// ---------------- attention coefficients for layer 0 only ----------------
__global__ __launch_bounds__(128) void as_kernel(const float* __restrict__ Xall, int l)
{
    const int n = blockIdx.x * 4 + (threadIdx.x >> 5);
    const int lane = threadIdx.x & 31;
    if (n >= Nn) return;
    const float* xp = Xall + (size_t)n * XSTR + l * Cc;
    float s[4] = {0.f, 0.f, 0.f, 0.f};
    float d[4] = {0.f, 0.f, 0.f, 0.f};
    #pragma unroll
    for (int j = 0; j < 4; j++) {
        int c = lane + j * 32;
        float xv = xp[c];
        float4 ws = *(const float4*)&g_Ws4[c * 4];
        float4 wd = *(const float4*)&g_Wd4[c * 4];
        s[0] = fmaf(xv, ws.x, s[0]); s[1] = fmaf(xv, ws.y, s[1]);
        s[2] = fmaf(xv, ws.z, s[2]); s[3] = fmaf(xv, ws.w, s[3]);
        d[0] = fmaf(xv, wd.x, d[0]); d[1] = fmaf(xv, wd.y, d[1]);
        d[2] = fmaf(xv, wd.z, d[2]); d[3] = fmaf(xv, wd.w, d[3]);
    }
    #pragma unroll
    for (int o = 16; o; o >>= 1) {
        #pragma unroll
        for (int h = 0; h < 4; h++) {
            s[h] += __shfl_xor_sync(0xffffffffu, s[h], o);
            d[h] += __shfl_xor_sync(0xffffffffu, d[h], o);
        }
    }
    if (lane == 0) {
        *(float4*)&g_as[n * 4] = make_float4(s[0], s[1], s[2], s[3]);
        *(float4*)&g_ad[n * 4] = make_float4(d[0], d[1], d[2], d[3]);
    }
}

// ---------------- edge phase: single-pass softmax + X-aggregation --------
// one 128-thread block per dst node; thread t owns channel t (all 4 heads).
// z[d, h*128+t] = (sum_s w_h(s) * X[s][t]) / (sum_s w_h(s)), stored bf16 hi/lo.
__global__ __launch_bounds__(128) void edge_kernel(const float* __restrict__ Xall, int l)
{
    const int d = blockIdx.x;
    const int tid = threadIdx.x;
    const int lane = tid & 31, wp = tid >> 5;
    const int r0 = g_rowptr[d];
    const int deg = g_rowptr[d + 1] - r0;
    const float4 ad = *(const float4*)(g_ad + d * 4);
    const float* Xl = Xall + l * Cc;

    __shared__ float4 red[4];
    __shared__ int    s_s[128];
    __shared__ float4 s_w[128];

    float a0 = 0.f, a1 = 0.f, a2 = 0.f, a3 = 0.f;
    float4 den = make_float4(0.f, 0.f, 0.f, 0.f);

    for (int base = 0; base < deg; base += 128) {
        int cnt = min(128, deg - base);
        if (tid < cnt) {
            int s = g_col[r0 + base + tid];
            float4 as = *(const float4*)(g_as + s * 4);
            float e0 = as.x + ad.x; e0 = fmaxf(e0, 0.2f * e0);
            float e1 = as.y + ad.y; e1 = fmaxf(e1, 0.2f * e1);
            float e2 = as.z + ad.z; e2 = fmaxf(e2, 0.2f * e2);
            float e3 = as.w + ad.w; e3 = fmaxf(e3, 0.2f * e3);
            float w0 = expf(e0), w1 = expf(e1);
            float w2 = expf(e2), w3 = expf(e3);
            s_s[tid] = s;
            s_w[tid] = make_float4(w0, w1, w2, w3);
            den.x += w0; den.y += w1; den.z += w2; den.w += w3;
        }
        __syncthreads();
        #pragma unroll 4
        for (int i = 0; i < cnt; i++) {
            float4 w = s_w[i];
            float xv = Xl[(size_t)s_s[i] * XSTR + tid];
            a0 = fmaf(w.x, xv, a0);
            a1 = fmaf(w.y, xv, a1);
            a2 = fmaf(w.z, xv, a2);
            a3 = fmaf(w.w, xv, a3);
        }
        __syncthreads();
    }

    // block-reduce denominator (all 4 heads needed by every thread)
    #pragma unroll
    for (int o = 16; o; o >>= 1) {
        den.x += __shfl_xor_sync(0xffffffffu, den.x, o);
        den.y += __shfl_xor_sync(0xffffffffu, den.y, o);
        den.z += __shfl_xor_sync(0xffffffffu, den.z, o);
        den.w += __shfl_xor_sync(0xffffffffu, den.w, o);
    }
    if (lane == 0) red[wp] = den;
    __syncthreads();
    float4 R;
    R.x = 1.0f / (red[0].x + red[1].x + red[2].x + red[3].x);
    R.y = 1.0f / (red[0].y + red[1].y + red[2].y + red[3].y);
    R.z = 1.0f / (red[0].z + red[1].z + red[2].z + red[3].z);
    R.w = 1.0f / (red[0].w + red[1].w + red[2].w + red[3].w);

    float av[4] = {a0 * R.x, a1 * R.y, a2 * R.z, a3 * R.w};
    __nv_bfloat16* zh = g_zhi + (size_t)d * Ff + tid;
    __nv_bfloat16* zl = g_zlo + (size_t)d * Ff + tid;
    #pragma unroll
    for (int h = 0; h < 4; h++) {
        __nv_bfloat16 hi = __float2bfloat16(av[h]);
        __nv_bfloat16 lo = __float2bfloat16(av[h] - __bfloat162float(hi));
        zh[h * 128] = hi;
        zl[h * 128] = lo;
    }
}

__device__ __forceinline__ void mma16816(float* c, const uint32_t* a, const uint32_t* b) {
    asm volatile("mma.sync.aligned.m16n8k16.row.col.f32.bf16.bf16.f32 "
        "{%0,%1,%2,%3}, {%4,%5,%6,%7}, {%8,%9}, {%0,%1,%2,%3};"
        : "+f"(c[0]), "+f"(c[1]), "+f"(c[2]), "+f"(c[3])
        : "r"(a[0]), "r"(a[1]), "r"(a[2]), "r"(a[3]), "r"(b[0]), "r"(b[1]));
}

// ---------------- GEMM: out = z_head @ W_head, fully fused epilogue ------
// A = z slice (bf16 pre-split), B = W^T block. Epilogue: bias+ELU+mean-of-4
// -> s_agg (smem), then coalesced X/Y update + next-layer a_s/a_d.
#define SM_AHI  0
#define SM_ALO  34816
#define SM_BHI  69632
#define SM_BLO  104448
#define SM_AGG  139264     // 128 rows x 132 floats (padded)   = 67584 B
#define SM_BIAS 206848     // 512 floats
#define SM_WS4  208896     // 512 floats
#define SM_WD4  210944     // 512 floats
#define SMEM_G2 212992

__global__ __launch_bounds__(256, 1) void gemm2_kernel(
    float* __restrict__ Xall, float* __restrict__ Yall,
    const float* __restrict__ bias, int l)
{
    extern __shared__ __align__(16) char smem[];
    const int tid = threadIdx.x;
    const int wid = tid >> 5, lane = tid & 31;
    const int g = lane >> 2, q = lane & 3;
    const int wm = wid & 1, wn = wid >> 1;       // 2 x 4 warp grid
    const int bm = blockIdx.x * 128;

    float* s_agg  = (float*)(smem + SM_AGG);
    float* s_bias = (float*)(smem + SM_BIAS);
    float* s_ws4  = (float*)(smem + SM_WS4);
    float* s_wd4  = (float*)(smem + SM_WD4);
    for (int i = tid; i < 512; i += 256) {
        s_bias[i] = bias[i];
        s_ws4[i]  = g_Ws4[i];
        s_wd4[i]  = g_Wd4[i];
    }

    const int a_base = (wm * 64 + g) * 272 + q * 4;
    const int b_base = (wn * 32 + g) * 272 + q * 4;

    float acc[4][4][4];

    for (int nt = 0; nt < 4; nt++) {
        const int bn = nt * 128;
        // ---- copy A tile (z head slice, bf16 hi/lo) ----
        #pragma unroll
        for (int it = 0; it < 8; it++) {
            int idx = it * 256 + tid;
            int r = idx >> 4, kg = idx & 15;
            size_t so = ((size_t)(bm + r) * Ff + bn + kg * 8) * 2;
            uint32_t off = (uint32_t)(r * 272 + kg * 16);
            *(uint4*)(smem + SM_AHI + off) = *(const uint4*)((const char*)g_zhi + so);
            *(uint4*)(smem + SM_ALO + off) = *(const uint4*)((const char*)g_zlo + so);
        }
        // ---- copy B tile (W^T block, bf16 hi/lo) ----
        #pragma unroll
        for (int it = 0; it < 8; it++) {
            int idx = it * 256 + tid;
            int r = idx >> 4, kg = idx & 15;
            size_t so = ((size_t)(bn + r) * Cc + kg * 8) * 2;
            uint32_t off = (uint32_t)(r * 272 + kg * 16);
            *(uint4*)(smem + SM_BHI + off) = *(const uint4*)((const char*)g_WThi + so);
            *(uint4*)(smem + SM_BLO + off) = *(const uint4*)((const char*)g_WTlo + so);
        }
        __syncthreads();

        #pragma unroll
        for (int mf = 0; mf < 4; mf++)
            #pragma unroll
            for (int nf = 0; nf < 4; nf++)
                #pragma unroll
                for (int j = 0; j < 4; j++) acc[mf][nf][j] = 0.f;

        #pragma unroll
        for (int ks = 0; ks < 8; ks++) {
            uint32_t bh[4][2], bl[4][2];
            #pragma unroll
            for (int nf = 0; nf < 4; nf++) {
                int bo = b_base + nf * 8 * 272 + ks * 32;
                bh[nf][0] = *(const uint32_t*)(smem + SM_BHI + bo);
                bh[nf][1] = *(const uint32_t*)(smem + SM_BHI + bo + 16);
                bl[nf][0] = *(const uint32_t*)(smem + SM_BLO + bo);
                bl[nf][1] = *(const uint32_t*)(smem + SM_BLO + bo + 16);
            }
            #pragma unroll
            for (int mf = 0; mf < 4; mf++) {
                int ao = a_base + mf * 16 * 272 + ks * 32;
                uint32_t ah[4], al[4];
                ah[0] = *(const uint32_t*)(smem + SM_AHI + ao);
                ah[1] = *(const uint32_t*)(smem + SM_AHI + ao + 2176);
                ah[2] = *(const uint32_t*)(smem + SM_AHI + ao + 16);
                ah[3] = *(const uint32_t*)(smem + SM_AHI + ao + 2176 + 16);
                al[0] = *(const uint32_t*)(smem + SM_ALO + ao);
                al[1] = *(const uint32_t*)(smem + SM_ALO + ao + 2176);
                al[2] = *(const uint32_t*)(smem + SM_ALO + ao + 16);
                al[3] = *(const uint32_t*)(smem + SM_ALO + ao + 2176 + 16);
                #pragma unroll
                for (int nf = 0; nf < 4; nf++) {
                    mma16816(acc[mf][nf], ah, bh[nf]);
                    mma16816(acc[mf][nf], ah, bl[nf]);
                    mma16816(acc[mf][nf], al, bh[nf]);
                }
            }
        }
        __syncthreads();   // A/B consumed; safe to reload next nt

        // ---- epilogue: bias+ELU+mean-of-4 -> s_agg ----
        #pragma unroll
        for (int mf = 0; mf < 4; mf++) {
            #pragma unroll
            for (int i = 0; i < 2; i++) {
                int row = wm * 64 + mf * 16 + i * 8 + g;
                #pragma unroll
                for (int nf = 0; nf < 4; nf++) {
                    int col = nt * 128 + wn * 32 + nf * 8 + q * 2;
                    float c0 = acc[mf][nf][i * 2]     + s_bias[col];
                    float c1 = acc[mf][nf][i * 2 + 1] + s_bias[col + 1];
                    c0 = c0 > 0.f ? c0 : expm1f(c0);
                    c1 = c1 > 0.f ? c1 : expm1f(c1);
                    float v = c0 + c1;
                    v += __shfl_xor_sync(0xffffffffu, v, 1);
                    if ((q & 1) == 0) {
                        int j = nt * 32 + wn * 8 + nf * 2 + (q >> 1);
                        s_agg[row * 132 + j] = 0.25f * v;
                    }
                }
            }
        }
    }
    __syncthreads();

    // ---- coalesced X/Y update ----
    for (int t = tid; t < 128 * 32; t += 256) {
        int row = t >> 5, c4 = (t & 31) << 2;
        int gm = bm + row;
        if (gm < Nn) {
            float4 a = *(const float4*)(s_agg + row * 132 + c4);
            size_t ofs = (size_t)gm * XSTR + (size_t)l * Cc + c4;
            float4 xold = *(const float4*)(Xall + ofs);
            *(float4*)(Xall + ofs + Cc) = a;
            *(float4*)(Yall + ofs + Cc) =
                make_float4(a.x - xold.x, a.y - xold.y, a.z - xold.z, a.w - xold.w);
        }
    }

    // ---- next-layer attention coefficients from s_agg ----
    if (l < 3 && tid < 128) {
        int gm = bm + tid;
        if (gm < Nn) {
            float s[4] = {0.f, 0.f, 0.f, 0.f};
            float d4[4] = {0.f, 0.f, 0.f, 0.f};
            #pragma unroll 4
            for (int j = 0; j < 128; j++) {
                float xv = s_agg[tid * 132 + j];
                float4 ws = *(const float4*)&s_ws4[j * 4];
                float4 wd = *(const float4*)&s_wd4[j * 4];
                s[0] = fmaf(xv, ws.x, s[0]); s[1] = fmaf(xv, ws.y, s[1]);
                s[2] = fmaf(xv, ws.z, s[2]); s[3] = fmaf(xv, ws.w, s[3]);
                d4[0] = fmaf(xv, wd.x, d4[0]); d4[1] = fmaf(xv, wd.y, d4[1]);
                d4[2] = fmaf(xv, wd.z, d4[2]); d4[3] = fmaf(xv, wd.w, d4[3]);
            }
            *(float4*)&g_as[gm * 4] = make_float4(s[0], s[1], s[2], s[3]);
            *(float4*)&g_ad[gm * 4] = make_float4(d4[0], d4[1], d4[2], d4[3]);
        }
    }
}

// ---------------- classifier: out = X4 @ Wr^T + br -----------------------
__global__ __launch_bounds__(64) void logits_kernel(const float* __restrict__ Xall,
                                                    const float* __restrict__ Wr,
                                                    const float* __restrict__ br,
                                                    float* __restrict__ out)
{
    __shared__ float Xs[32 * 132];
    __shared__ float Ws[40 * 132];
    __shared__ float bs[40];
    const int tid = threadIdx.x;
    const int bmn = blockIdx.x * 32;

    for (int f = tid; f < 32 * 32; f += 64) {
        int r = f >> 5, k4 = (f & 31) << 2;
        int g = bmn + r;
        float4 v = make_float4(0.f, 0.f, 0.f, 0.f);
        if (g < Nn) v = *(const float4*)(Xall + (size_t)g * XSTR + 4 * Cc + k4);
        *(float4*)(Xs + r * 132 + k4) = v;
    }
    for (int f = tid; f < 40 * 32; f += 64) {
        int r = f >> 5, k4 = (f & 31) << 2;
        *(float4*)(Ws + r * 132 + k4) = *(const float4*)(Wr + (size_t)r * Cc + k4);
    }
    if (tid < 40) bs[tid] = br[tid];
    __syncthreads();

    const int ty = tid >> 3, tx = tid & 7;
    float acc[4][5];
    #pragma unroll
    for (int i = 0; i < 4; i++)
        #pragma unroll
        for (int j = 0; j < 5; j++) acc[i][j] = 0.f;

    #pragma unroll 4
    for (int k = 0; k < 128; k++) {
        float a[4], b[5];
        #pragma unroll
        for (int i = 0; i < 4; i++) a[i] = Xs[(ty * 4 + i) * 132 + k];
        #pragma unroll
        for (int j = 0; j < 5; j++) b[j] = Ws[(tx * 5 + j) * 132 + k];
        #pragma unroll
        for (int i = 0; i < 4; i++)
            #pragma unroll
            for (int j = 0; j < 5; j++) acc[i][j] = fmaf(a[i], b[j], acc[i][j]);
    }
    #pragma unroll
    for (int i = 0; i < 4; i++) {
        int g = bmn + ty * 4 + i;
        if (g < Nn)
            #pragma unroll
            for (int j = 0; j < 5; j++)
                out[(size_t)g * NCLS + tx * 5 + j] = acc[i][j] + bs[tx * 5 + j];
    }
}

// ---------------- launch --------------------------------------------------
extern "C" void kernel_launch(void* const* d_in, const int* in_sizes, int n_in,
                              void* d_out, int out_size)
{
    const float* x     = (const float*)d_in[0];
    const int*   src   = (const int*)  d_in[1];
    const int*   dst   = (const int*)  d_in[2];
    const float* W     = (const float*)d_in[3];
    const float* att_s = (const float*)d_in[4];
    const float* att_d = (const float*)d_in[5];
    const float* bias  = (const float*)d_in[6];
    const float* Wr    = (const float*)d_in[7];
    const float* br    = (const float*)d_in[8];

    float* out  = (float*)d_out;
    float* Xall = out + (size_t)Nn * NCLS;            // [N, 5, 128]
    float* Yall = Xall + (size_t)Nn * 5 * Cc;         // [N, 5, 128]

    cudaFuncSetAttribute(gemm2_kernel, cudaFuncAttributeMaxDynamicSharedMemorySize,
                         SMEM_G2);

    init_kernel<<<(Nn * Cc + 255) / 256, 256>>>(x, Xall, Yall);
    split_w_kernel<<<(Cc * Ff + 255) / 256, 256>>>(W);
    prep_att_kernel<<<1, 512>>>(W, att_s, att_d);
    count_kernel<<<(ET + 255) / 256, 256>>>(dst);
    scan_kernel<<<1, 1024>>>();
    fill_kernel<<<(ET + 255) / 256, 256>>>(src, dst);
    as_kernel<<<(Nn + 3) / 4, 128>>>(Xall, 0);

    for (int l = 0; l < 4; l++) {
        edge_kernel<<<Nn, 128>>>(Xall, l);
        gemm2_kernel<<<157, 256, SMEM_G2>>>(Xall, Yall, bias, l);
    }
    logits_kernel<<<(Nn + 31) / 32, 64>>>(Xall, Wr, br, out);
}

// round 13
// speedup vs baseline: 1.4362x; 1.4362x over previous
#include <cuda_runtime.h>
#include <cuda_bf16.h>
#include <cuda_fp16.h>
#include <math.h>
#include <cstdint>

#define Nn    20000
#define Cc    128
#define Ff    512        // HEADS*NHID
#define Ee    320000
#define ET    340000     // E + N self loops
#define XSTR  640        // (NLAYERS+1)*Cc
#define NCLS  40

// ---------------- scratch (no dynamic allocation allowed) ----------------
__device__ __half g_h[(size_t)Nn * Ff];    // h = X @ W  [N, 512]  (fp16)
__device__ float g_as[Nn * 4];             // a_src per node per head
__device__ float g_ad[Nn * 4];             // a_dst per node per head
__device__ int   g_rowptr[Nn + 1];
__device__ int   g_fill[Nn];
__device__ int   g_cnt[Nn];
__device__ int   g_col[ET];
__device__ __nv_bfloat16 g_WThi[Ff * Cc];  // W^T split hi  [n=512][k=128]
__device__ __nv_bfloat16 g_WTlo[Ff * Cc];  // W^T split lo

// ---------------- init ---------------------------------------------------
__global__ void init_kernel(const float* __restrict__ x,
                            float* __restrict__ Xall, float* __restrict__ Yall)
{
    int i = blockIdx.x * blockDim.x + threadIdx.x;
    if (i < Nn * Cc) {
        int n = i >> 7, c = i & 127;
        float v = x[i];
        Xall[(size_t)n * XSTR + c] = v;
        Yall[(size_t)n * XSTR + c] = v;
    }
    if (i < Nn) g_cnt[i] = 0;
}

// ---------------- one-time W transpose + bf16 split ----------------------
__global__ void split_w_kernel(const float* __restrict__ W)
{
    int i = blockIdx.x * blockDim.x + threadIdx.x;
    if (i < Cc * Ff) {
        int k = i >> 9, n = i & 511;
        float w = W[i];
        __nv_bfloat16 hi = __float2bfloat16(w);
        __nv_bfloat16 lo = __float2bfloat16(w - __bfloat162float(hi));
        g_WThi[n * Cc + k] = hi;
        g_WTlo[n * Cc + k] = lo;
    }
}

// ---------------- CSR build (by dst, self-loops appended) ----------------
__global__ void count_kernel(const int* __restrict__ dst)
{
    int i = blockIdx.x * blockDim.x + threadIdx.x;
    if (i < ET) {
        int d = (i < Ee) ? dst[i] : (i - Ee);
        atomicAdd(&g_cnt[d], 1);
    }
}

// SMEM-staged scan: coalesced global I/O, per-thread chunks from SMEM.
// rowptr[i] == fill[i] == exclusive prefix; rowptr[Nn] = ET (constant).
#define SCAN_SMEM (20480 * 4)
__global__ void scan_kernel()
{
    extern __shared__ int sbuf[];
    __shared__ int wsum[32];
    const int t = threadIdx.x, lane = t & 31, wp = t >> 5;

    for (int i = t; i < 20480; i += 1024)
        sbuf[i] = (i < Nn) ? g_cnt[i] : 0;
    __syncthreads();

    int v[20], sum = 0;
    #pragma unroll
    for (int i = 0; i < 20; i++) { v[i] = sbuf[t * 20 + i]; sum += v[i]; }

    int x = sum;
    #pragma unroll
    for (int o = 1; o < 32; o <<= 1) {
        int u = __shfl_up_sync(0xffffffffu, x, o);
        if (lane >= o) x += u;
    }
    if (lane == 31) wsum[wp] = x;
    __syncthreads();
    if (wp == 0) {
        int y = wsum[lane];
        #pragma unroll
        for (int o = 1; o < 32; o <<= 1) {
            int u = __shfl_up_sync(0xffffffffu, y, o);
            if (lane >= o) y += u;
        }
        wsum[lane] = y;
    }
    __syncthreads();

    int run = x - sum + (wp ? wsum[wp - 1] : 0);
    #pragma unroll
    for (int i = 0; i < 20; i++) { sbuf[t * 20 + i] = run; run += v[i]; }
    __syncthreads();

    for (int i = t; i < Nn; i += 1024) {
        int p = sbuf[i];
        g_fill[i]   = p;
        g_rowptr[i] = p;
    }
    if (t == 0) g_rowptr[Nn] = ET;
}

__global__ void fill_kernel(const int* __restrict__ src, const int* __restrict__ dst)
{
    int i = blockIdx.x * blockDim.x + threadIdx.x;
    if (i < ET) {
        int s, d;
        if (i < Ee) { s = src[i]; d = dst[i]; }
        else        { s = d = i - Ee; }
        int p = atomicAdd(&g_fill[d], 1);
        g_col[p] = s;
    }
}

// ---------------- bf16 split helper --------------------------------------
__device__ __forceinline__ void split2(float a0, float a1, uint32_t& hi, uint32_t& lo) {
    __nv_bfloat16 h0 = __float2bfloat16(a0);
    __nv_bfloat16 h1 = __float2bfloat16(a1);
    __nv_bfloat16 l0 = __float2bfloat16(a0 - __bfloat162float(h0));
    __nv_bfloat16 l1 = __float2bfloat16(a1 - __bfloat162float(h1));
    hi = (uint32_t)__bfloat16_as_ushort(h0) | ((uint32_t)__bfloat16_as_ushort(h1) << 16);
    lo = (uint32_t)__bfloat16_as_ushort(l0) | ((uint32_t)__bfloat16_as_ushort(l1) << 16);
}

__device__ __forceinline__ void mma16816(float* c, const uint32_t* a, const uint32_t* b) {
    asm volatile("mma.sync.aligned.m16n8k16.row.col.f32.bf16.bf16.f32 "
        "{%0,%1,%2,%3}, {%4,%5,%6,%7}, {%8,%9}, {%0,%1,%2,%3};"
        : "+f"(c[0]), "+f"(c[1]), "+f"(c[2]), "+f"(c[3])
        : "r"(a[0]), "r"(a[1]), "r"(a[2]), "r"(a[3]), "r"(b[0]), "r"(b[1]));
}

// ---------------- mma.sync GEMM + fused attention coefficients -----------
// One CTA = 128 rows, loops over 4 n-tiles of 128 cols (whole Ff=512).
// bf16x3: h = Ahi*Bhi + Ahi*Blo + Alo*Bhi (fp32 accumulate). h stored fp16.
#define SM_AHI  0
#define SM_ALO  34816      // 128 rows * 272B
#define SM_BHI  69632
#define SM_BLO  104448
#define SM_ATTS 139264     // 512 floats
#define SM_ATTD 141312     // 512 floats
#define SM_AS   143360     // 512 floats (128 rows x 4 heads)
#define SM_AD   145408     // 512 floats
#define SMEM_MG 147456

__global__ __launch_bounds__(256, 1) void mma_gemm_kernel(
    const float* __restrict__ Xall, int loff,
    const float* __restrict__ att_s, const float* __restrict__ att_d)
{
    extern __shared__ __align__(16) char smem[];
    const int tid = threadIdx.x;
    const int wid = tid >> 5, lane = tid & 31;
    const int g = lane >> 2, q = lane & 3;
    const int wm = wid & 1, wn = wid >> 1;       // 2 x 4 warp grid
    const int bm = blockIdx.x * 128;

    float* s_atts = (float*)(smem + SM_ATTS);
    float* s_attd = (float*)(smem + SM_ATTD);
    float* s_as   = (float*)(smem + SM_AS);
    float* s_ad   = (float*)(smem + SM_AD);

    for (int i = tid; i < 512; i += 256) {
        s_atts[i] = att_s[i];
        s_attd[i] = att_d[i];
        s_as[i] = 0.f;
        s_ad[i] = 0.f;
    }

    // ---- load + split A tile (128 rows x 128 k), stride 272B, hi/lo ----
    #pragma unroll
    for (int it = 0; it < 8; it++) {
        int idx = it * 256 + tid;        // 0..2047
        int r   = idx >> 4;              // row 0..127
        int kg  = idx & 15;              // 8-elem group
        int gm  = bm + r;
        float v[8];
        if (gm < Nn) {
            const float* p = Xall + (size_t)gm * XSTR + loff + kg * 8;
            float4 u0 = *(const float4*)p;
            float4 u1 = *(const float4*)(p + 4);
            v[0]=u0.x; v[1]=u0.y; v[2]=u0.z; v[3]=u0.w;
            v[4]=u1.x; v[5]=u1.y; v[6]=u1.z; v[7]=u1.w;
        } else {
            #pragma unroll
            for (int j = 0; j < 8; j++) v[j] = 0.f;
        }
        uint32_t hi[4], lo[4];
        #pragma unroll
        for (int j = 0; j < 4; j++) split2(v[2*j], v[2*j+1], hi[j], lo[j]);
        uint32_t off = (uint32_t)(r * 272 + kg * 16);
        *(uint4*)(smem + SM_AHI + off) = make_uint4(hi[0], hi[1], hi[2], hi[3]);
        *(uint4*)(smem + SM_ALO + off) = make_uint4(lo[0], lo[1], lo[2], lo[3]);
    }

    const int a_base = (wm * 64 + g) * 272 + q * 4;
    const int b_base = (wn * 32 + g) * 272 + q * 4;

    float acc[4][4][4];

    for (int nt = 0; nt < 4; nt++) {
        // ---- copy B tile (128 n-rows x 128 k bf16, hi+lo) ----
        const int bn = nt * 128;
        #pragma unroll
        for (int it = 0; it < 8; it++) {
            int idx = it * 256 + tid;
            int r = idx >> 4, kg = idx & 15;
            uint32_t off = (uint32_t)(r * 272 + kg * 16);
            *(uint4*)(smem + SM_BHI + off) =
                *(const uint4*)((const char*)g_WThi + ((size_t)(bn + r) * Cc + kg * 8) * 2);
            *(uint4*)(smem + SM_BLO + off) =
                *(const uint4*)((const char*)g_WTlo + ((size_t)(bn + r) * Cc + kg * 8) * 2);
        }
        __syncthreads();

        #pragma unroll
        for (int mf = 0; mf < 4; mf++)
            #pragma unroll
            for (int nf = 0; nf < 4; nf++)
                #pragma unroll
                for (int j = 0; j < 4; j++) acc[mf][nf][j] = 0.f;

        // ---- K loop: 8 steps of k16 ----
        #pragma unroll
        for (int ks = 0; ks < 8; ks++) {
            uint32_t bh[4][2], bl[4][2];
            #pragma unroll
            for (int nf = 0; nf < 4; nf++) {
                int bo = b_base + nf * 8 * 272 + ks * 32;
                bh[nf][0] = *(const uint32_t*)(smem + SM_BHI + bo);
                bh[nf][1] = *(const uint32_t*)(smem + SM_BHI + bo + 16);
                bl[nf][0] = *(const uint32_t*)(smem + SM_BLO + bo);
                bl[nf][1] = *(const uint32_t*)(smem + SM_BLO + bo + 16);
            }
            #pragma unroll
            for (int mf = 0; mf < 4; mf++) {
                int ao = a_base + mf * 16 * 272 + ks * 32;
                uint32_t ah[4], al[4];
                ah[0] = *(const uint32_t*)(smem + SM_AHI + ao);
                ah[1] = *(const uint32_t*)(smem + SM_AHI + ao + 2176);
                ah[2] = *(const uint32_t*)(smem + SM_AHI + ao + 16);
                ah[3] = *(const uint32_t*)(smem + SM_AHI + ao + 2176 + 16);
                al[0] = *(const uint32_t*)(smem + SM_ALO + ao);
                al[1] = *(const uint32_t*)(smem + SM_ALO + ao + 2176);
                al[2] = *(const uint32_t*)(smem + SM_ALO + ao + 16);
                al[3] = *(const uint32_t*)(smem + SM_ALO + ao + 2176 + 16);
                #pragma unroll
                for (int nf = 0; nf < 4; nf++) {
                    mma16816(acc[mf][nf], ah, bh[nf]);
                    mma16816(acc[mf][nf], ah, bl[nf]);
                    mma16816(acc[mf][nf], al, bh[nf]);
                }
            }
        }

        // ---- epilogue: write h (fp16), accumulate attention dots (fp32) ----
        #pragma unroll
        for (int mf = 0; mf < 4; mf++) {
            #pragma unroll
            for (int i = 0; i < 2; i++) {
                int row = wm * 64 + mf * 16 + i * 8 + g;
                int gm  = bm + row;
                float as_p = 0.f, ad_p = 0.f;
                #pragma unroll
                for (int nf = 0; nf < 4; nf++) {
                    float c0 = acc[mf][nf][i * 2];
                    float c1 = acc[mf][nf][i * 2 + 1];
                    int col = nt * 128 + wn * 32 + nf * 8 + q * 2;
                    if (gm < Nn)
                        *(__half2*)(g_h + (size_t)gm * Ff + col) = __floats2half2_rn(c0, c1);
                    as_p += c0 * s_atts[col] + c1 * s_atts[col + 1];
                    ad_p += c0 * s_attd[col] + c1 * s_attd[col + 1];
                }
                as_p += __shfl_xor_sync(0xffffffffu, as_p, 1);
                as_p += __shfl_xor_sync(0xffffffffu, as_p, 2);
                ad_p += __shfl_xor_sync(0xffffffffu, ad_p, 1);
                ad_p += __shfl_xor_sync(0xffffffffu, ad_p, 2);
                if (q == 0) {
                    atomicAdd(&s_as[row * 4 + nt], as_p);   // head == nt
                    atomicAdd(&s_ad[row * 4 + nt], ad_p);
                }
            }
        }
        __syncthreads();
    }

    // ---- write attention coefficients ----
    for (int i = tid; i < 512; i += 256) {
        int row = i >> 2;
        int gm = bm + row;
        if (gm < Nn) {
            g_as[gm * 4 + (i & 3)] = s_as[i];
            g_ad[gm * 4 + (i & 3)] = s_ad[i];
        }
    }
}

// ---------------- edge phase: single-pass softmax + aggregate + update ---
// alpha = w/sum(w), w = exp(e) (shift-free); agg = (sum w*h)/(sum w).
// h gathered as fp16 (uint2 = 4 halves per thread).
__global__ __launch_bounds__(128) void edge_kernel(const float* __restrict__ bias,
                                                   float* __restrict__ Xall,
                                                   float* __restrict__ Yall, int l)
{
    const int d = blockIdx.x;
    const int tid = threadIdx.x;
    const int lane = tid & 31, wp = tid >> 5;
    const int r0 = g_rowptr[d];
    const int deg = g_rowptr[d + 1] - r0;
    const float4 ad = *(const float4*)(g_ad + d * 4);

    __shared__ float4 red[4];
    __shared__ int    s_s[128];
    __shared__ float4 s_w[128];

    float4 acc = make_float4(0.f, 0.f, 0.f, 0.f);
    float4 den = make_float4(0.f, 0.f, 0.f, 0.f);

    for (int base = 0; base < deg; base += 128) {
        int cnt = min(128, deg - base);
        if (tid < cnt) {
            int s = g_col[r0 + base + tid];
            float4 as = *(const float4*)(g_as + s * 4);
            float e0 = as.x + ad.x; e0 = fmaxf(e0, 0.2f * e0);
            float e1 = as.y + ad.y; e1 = fmaxf(e1, 0.2f * e1);
            float e2 = as.z + ad.z; e2 = fmaxf(e2, 0.2f * e2);
            float e3 = as.w + ad.w; e3 = fmaxf(e3, 0.2f * e3);
            float w0 = expf(e0), w1 = expf(e1);
            float w2 = expf(e2), w3 = expf(e3);
            s_s[tid] = s;
            s_w[tid] = make_float4(w0, w1, w2, w3);
            den.x += w0; den.y += w1; den.z += w2; den.w += w3;
        }
        __syncthreads();
        const float* wf = (const float*)s_w;
        #pragma unroll 4
        for (int i = 0; i < cnt; i++) {
            float w = wf[i * 4 + wp];
            uint2 u = *(const uint2*)(g_h + (size_t)s_s[i] * Ff + tid * 4);
            float2 f0 = __half22float2(*(const __half2*)&u.x);
            float2 f1 = __half22float2(*(const __half2*)&u.y);
            acc.x = fmaf(w, f0.x, acc.x);
            acc.y = fmaf(w, f0.y, acc.y);
            acc.z = fmaf(w, f1.x, acc.z);
            acc.w = fmaf(w, f1.y, acc.w);
        }
        __syncthreads();
    }

    // block-reduce denominator (per head)
    #pragma unroll
    for (int o = 16; o; o >>= 1) {
        den.x += __shfl_xor_sync(0xffffffffu, den.x, o);
        den.y += __shfl_xor_sync(0xffffffffu, den.y, o);
        den.z += __shfl_xor_sync(0xffffffffu, den.z, o);
        den.w += __shfl_xor_sync(0xffffffffu, den.w, o);
    }
    if (lane == 0) red[wp] = den;
    __syncthreads();
    float4 D;
    D.x = red[0].x + red[1].x + red[2].x + red[3].x;
    D.y = red[0].y + red[1].y + red[2].y + red[3].y;
    D.z = red[0].z + red[1].z + red[2].z + red[3].z;
    D.w = red[0].w + red[1].w + red[2].w + red[3].w;
    float dh = (wp == 0) ? D.x : (wp == 1) ? D.y : (wp == 2) ? D.z : D.w;
    float R = 1.0f / dh;

    // + bias, ELU, regroup-mean (flat 4t..4t+3 -> agg[t]), GraphCON update
    float4 b = *(const float4*)(bias + tid * 4);
    float v0 = acc.x * R + b.x; v0 = v0 > 0.f ? v0 : expm1f(v0);
    float v1 = acc.y * R + b.y; v1 = v1 > 0.f ? v1 : expm1f(v1);
    float v2 = acc.z * R + b.z; v2 = v2 > 0.f ? v2 : expm1f(v2);
    float v3 = acc.w * R + b.w; v3 = v3 > 0.f ? v3 : expm1f(v3);
    float agg = 0.25f * (v0 + v1 + v2 + v3);

    size_t ofs = (size_t)d * XSTR + (size_t)l * Cc + tid;
    float xold = Xall[ofs];
    Xall[ofs + Cc] = agg;            // X_{l+1} = agg
    Yall[ofs + Cc] = agg - xold;     // Y_{l+1} = agg - X_l
}

// ---------------- classifier: out = X4 @ Wr^T + br -----------------------
__global__ __launch_bounds__(64) void logits_kernel(const float* __restrict__ Xall,
                                                    const float* __restrict__ Wr,
                                                    const float* __restrict__ br,
                                                    float* __restrict__ out)
{
    __shared__ float Xs[32 * 132];
    __shared__ float Ws[40 * 132];
    __shared__ float bs[40];
    const int tid = threadIdx.x;
    const int bmn = blockIdx.x * 32;

    for (int f = tid; f < 32 * 32; f += 64) {
        int r = f >> 5, k4 = (f & 31) << 2;
        int g = bmn + r;
        float4 v = make_float4(0.f, 0.f, 0.f, 0.f);
        if (g < Nn) v = *(const float4*)(Xall + (size_t)g * XSTR + 4 * Cc + k4);
        *(float4*)(Xs + r * 132 + k4) = v;
    }
    for (int f = tid; f < 40 * 32; f += 64) {
        int r = f >> 5, k4 = (f & 31) << 2;
        *(float4*)(Ws + r * 132 + k4) = *(const float4*)(Wr + (size_t)r * Cc + k4);
    }
    if (tid < 40) bs[tid] = br[tid];
    __syncthreads();

    const int ty = tid >> 3, tx = tid & 7;
    float acc[4][5];
    #pragma unroll
    for (int i = 0; i < 4; i++)
        #pragma unroll
        for (int j = 0; j < 5; j++) acc[i][j] = 0.f;

    #pragma unroll 4
    for (int k = 0; k < 128; k++) {
        float a[4], b[5];
        #pragma unroll
        for (int i = 0; i < 4; i++) a[i] = Xs[(ty * 4 + i) * 132 + k];
        #pragma unroll
        for (int j = 0; j < 5; j++) b[j] = Ws[(tx * 5 + j) * 132 + k];
        #pragma unroll
        for (int i = 0; i < 4; i++)
            #pragma unroll
            for (int j = 0; j < 5; j++) acc[i][j] = fmaf(a[i], b[j], acc[i][j]);
    }
    #pragma unroll
    for (int i = 0; i < 4; i++) {
        int g = bmn + ty * 4 + i;
        if (g < Nn)
            #pragma unroll
            for (int j = 0; j < 5; j++)
                out[(size_t)g * NCLS + tx * 5 + j] = acc[i][j] + bs[tx * 5 + j];
    }
}

// ---------------- launch --------------------------------------------------
extern "C" void kernel_launch(void* const* d_in, const int* in_sizes, int n_in,
                              void* d_out, int out_size)
{
    const float* x     = (const float*)d_in[0];
    const int*   src   = (const int*)  d_in[1];
    const int*   dst   = (const int*)  d_in[2];
    const float* W     = (const float*)d_in[3];
    const float* att_s = (const float*)d_in[4];
    const float* att_d = (const float*)d_in[5];
    const float* bias  = (const float*)d_in[6];
    const float* Wr    = (const float*)d_in[7];
    const float* br    = (const float*)d_in[8];

    float* out  = (float*)d_out;
    float* Xall = out + (size_t)Nn * NCLS;            // [N, 5, 128]
    float* Yall = Xall + (size_t)Nn * 5 * Cc;         // [N, 5, 128]

    cudaFuncSetAttribute(mma_gemm_kernel, cudaFuncAttributeMaxDynamicSharedMemorySize,
                         SMEM_MG);
    cudaFuncSetAttribute(scan_kernel, cudaFuncAttributeMaxDynamicSharedMemorySize,
                         SCAN_SMEM);

    init_kernel<<<(Nn * Cc + 255) / 256, 256>>>(x, Xall, Yall);
    split_w_kernel<<<(Cc * Ff + 255) / 256, 256>>>(W);
    count_kernel<<<(ET + 255) / 256, 256>>>(dst);
    scan_kernel<<<1, 1024, SCAN_SMEM>>>();
    fill_kernel<<<(ET + 255) / 256, 256>>>(src, dst);

    for (int l = 0; l < 4; l++) {
        mma_gemm_kernel<<<157, 256, SMEM_MG>>>(Xall, l * Cc, att_s, att_d);
        edge_kernel<<<Nn, 128>>>(bias, Xall, Yall, l);
    }
    logits_kernel<<<(Nn + 31) / 32, 64>>>(Xall, Wr, br, out);
}

// round 16
// speedup vs baseline: 1.5694x; 1.0928x over previous
#include <cuda_runtime.h>
#include <cuda_bf16.h>
#include <cuda_fp16.h>
#include <math.h>
#include <cstdint>

#define Nn    20000
#define Cc    128
#define Ff    512        // HEADS*NHID
#define Ee    320000
#define ET    340000     // E + N self loops
#define XSTR  640        // (NLAYERS+1)*Cc
#define NCLS  40

// ---------------- scratch (no dynamic allocation allowed) ----------------
__device__ __half g_h[(size_t)Nn * Ff];    // h = X @ W  [N, 512]  (fp16)
__device__ float g_as[Nn * 4];             // a_src per node per head
__device__ float g_ad[Nn * 4];             // a_dst per node per head
__device__ int   g_rowptr[Nn + 1];
__device__ int   g_fill[Nn];
__device__ int   g_cnt[Nn];
__device__ int   g_col[ET];
__device__ __nv_bfloat16 g_WThi[Ff * Cc];  // W^T split hi  [n=512][k=128]
__device__ __nv_bfloat16 g_WTlo[Ff * Cc];  // W^T split lo

// ---------------- init ---------------------------------------------------
__global__ void init_kernel(const float* __restrict__ x,
                            float* __restrict__ Xall, float* __restrict__ Yall)
{
    int i = blockIdx.x * blockDim.x + threadIdx.x;
    if (i < Nn * Cc) {
        int n = i >> 7, c = i & 127;
        float v = x[i];
        Xall[(size_t)n * XSTR + c] = v;
        Yall[(size_t)n * XSTR + c] = v;
    }
    if (i < Nn) g_cnt[i] = 0;
}

// ---------------- one-time W transpose + bf16 split ----------------------
__global__ void split_w_kernel(const float* __restrict__ W)
{
    int i = blockIdx.x * blockDim.x + threadIdx.x;
    if (i < Cc * Ff) {
        int k = i >> 9, n = i & 511;
        float w = W[i];
        __nv_bfloat16 hi = __float2bfloat16(w);
        __nv_bfloat16 lo = __float2bfloat16(w - __bfloat162float(hi));
        g_WThi[n * Cc + k] = hi;
        g_WTlo[n * Cc + k] = lo;
    }
}

// ---------------- CSR build (by dst, self-loops appended) ----------------
__global__ void count_kernel(const int* __restrict__ dst)
{
    int i = blockIdx.x * blockDim.x + threadIdx.x;
    if (i < ET) {
        int d = (i < Ee) ? dst[i] : (i - Ee);
        atomicAdd(&g_cnt[d], 1);
    }
}

// SMEM-staged scan: coalesced global I/O, per-thread chunks from SMEM.
#define SCAN_SMEM (20480 * 4)
__global__ void scan_kernel()
{
    extern __shared__ int sbuf[];
    __shared__ int wsum[32];
    const int t = threadIdx.x, lane = t & 31, wp = t >> 5;

    for (int i = t; i < 20480; i += 1024)
        sbuf[i] = (i < Nn) ? g_cnt[i] : 0;
    __syncthreads();

    int v[20], sum = 0;
    #pragma unroll
    for (int i = 0; i < 20; i++) { v[i] = sbuf[t * 20 + i]; sum += v[i]; }

    int x = sum;
    #pragma unroll
    for (int o = 1; o < 32; o <<= 1) {
        int u = __shfl_up_sync(0xffffffffu, x, o);
        if (lane >= o) x += u;
    }
    if (lane == 31) wsum[wp] = x;
    __syncthreads();
    if (wp == 0) {
        int y = wsum[lane];
        #pragma unroll
        for (int o = 1; o < 32; o <<= 1) {
            int u = __shfl_up_sync(0xffffffffu, y, o);
            if (lane >= o) y += u;
        }
        wsum[lane] = y;
    }
    __syncthreads();

    int run = x - sum + (wp ? wsum[wp - 1] : 0);
    #pragma unroll
    for (int i = 0; i < 20; i++) { sbuf[t * 20 + i] = run; run += v[i]; }
    __syncthreads();

    for (int i = t; i < Nn; i += 1024) {
        int p = sbuf[i];
        g_fill[i]   = p;
        g_rowptr[i] = p;
    }
    if (t == 0) g_rowptr[Nn] = ET;
}

__global__ void fill_kernel(const int* __restrict__ src, const int* __restrict__ dst)
{
    int i = blockIdx.x * blockDim.x + threadIdx.x;
    if (i < ET) {
        int s, d;
        if (i < Ee) { s = src[i]; d = dst[i]; }
        else        { s = d = i - Ee; }
        int p = atomicAdd(&g_fill[d], 1);
        g_col[p] = s;
    }
}

// ---------------- bf16 split helper --------------------------------------
__device__ __forceinline__ void split2(float a0, float a1, uint32_t& hi, uint32_t& lo) {
    __nv_bfloat16 h0 = __float2bfloat16(a0);
    __nv_bfloat16 h1 = __float2bfloat16(a1);
    __nv_bfloat16 l0 = __float2bfloat16(a0 - __bfloat162float(h0));
    __nv_bfloat16 l1 = __float2bfloat16(a1 - __bfloat162float(h1));
    hi = (uint32_t)__bfloat16_as_ushort(h0) | ((uint32_t)__bfloat16_as_ushort(h1) << 16);
    lo = (uint32_t)__bfloat16_as_ushort(l0) | ((uint32_t)__bfloat16_as_ushort(l1) << 16);
}

__device__ __forceinline__ void mma16816(float* c, const uint32_t* a, const uint32_t* b) {
    asm volatile("mma.sync.aligned.m16n8k16.row.col.f32.bf16.bf16.f32 "
        "{%0,%1,%2,%3}, {%4,%5,%6,%7}, {%8,%9}, {%0,%1,%2,%3};"
        : "+f"(c[0]), "+f"(c[1]), "+f"(c[2]), "+f"(c[3])
        : "r"(a[0]), "r"(a[1]), "r"(a[2]), "r"(a[3]), "r"(b[0]), "r"(b[1]));
}

// ---------------- mma.sync GEMM + fused attention coefficients -----------
// Grid (157, 2): blockIdx.y selects heads {0,1} or {2,3} (2 n-tiles of 128).
// bf16x3: h = Ahi*Bhi + Ahi*Blo + Alo*Bhi (fp32 accumulate). h stored fp16.
#define SM_AHI  0
#define SM_ALO  34816      // 128 rows * 272B
#define SM_BHI  69632
#define SM_BLO  104448
#define SM_ATTS 139264     // 512 floats
#define SM_ATTD 141312     // 512 floats
#define SM_AS   143360     // 256 floats (128 rows x 2 heads)
#define SM_AD   144384     // 256 floats
#define SMEM_MG 145408

__global__ __launch_bounds__(256, 1) void mma_gemm_kernel(
    const float* __restrict__ Xall, int loff,
    const float* __restrict__ att_s, const float* __restrict__ att_d)
{
    extern __shared__ __align__(16) char smem[];
    const int tid = threadIdx.x;
    const int wid = tid >> 5, lane = tid & 31;
    const int g = lane >> 2, q = lane & 3;
    const int wm = wid & 1, wn = wid >> 1;       // 2 x 4 warp grid
    const int bm = blockIdx.x * 128;
    const int half = blockIdx.y;                 // head pair {2h, 2h+1}

    float* s_atts = (float*)(smem + SM_ATTS);
    float* s_attd = (float*)(smem + SM_ATTD);
    float* s_as   = (float*)(smem + SM_AS);
    float* s_ad   = (float*)(smem + SM_AD);

    for (int i = tid; i < 512; i += 256) {
        s_atts[i] = att_s[i];
        s_attd[i] = att_d[i];
    }
    if (tid < 256) { s_as[tid] = 0.f; s_ad[tid] = 0.f; }

    // ---- load + split A tile (128 rows x 128 k), stride 272B, hi/lo ----
    #pragma unroll
    for (int it = 0; it < 8; it++) {
        int idx = it * 256 + tid;        // 0..2047
        int r   = idx >> 4;              // row 0..127
        int kg  = idx & 15;              // 8-elem group
        int gm  = bm + r;
        float v[8];
        if (gm < Nn) {
            const float* p = Xall + (size_t)gm * XSTR + loff + kg * 8;
            float4 u0 = *(const float4*)p;
            float4 u1 = *(const float4*)(p + 4);
            v[0]=u0.x; v[1]=u0.y; v[2]=u0.z; v[3]=u0.w;
            v[4]=u1.x; v[5]=u1.y; v[6]=u1.z; v[7]=u1.w;
        } else {
            #pragma unroll
            for (int j = 0; j < 8; j++) v[j] = 0.f;
        }
        uint32_t hi[4], lo[4];
        #pragma unroll
        for (int j = 0; j < 4; j++) split2(v[2*j], v[2*j+1], hi[j], lo[j]);
        uint32_t off = (uint32_t)(r * 272 + kg * 16);
        *(uint4*)(smem + SM_AHI + off) = make_uint4(hi[0], hi[1], hi[2], hi[3]);
        *(uint4*)(smem + SM_ALO + off) = make_uint4(lo[0], lo[1], lo[2], lo[3]);
    }

    const int a_base = (wm * 64 + g) * 272 + q * 4;
    const int b_base = (wn * 32 + g) * 272 + q * 4;

    float acc[4][4][4];

    for (int ht = 0; ht < 2; ht++) {
        const int nt = half * 2 + ht;            // global n-tile / head
        const int bn = nt * 128;
        // ---- copy B tile (128 n-rows x 128 k bf16, hi+lo) ----
        #pragma unroll
        for (int it = 0; it < 8; it++) {
            int idx = it * 256 + tid;
            int r = idx >> 4, kg = idx & 15;
            uint32_t off = (uint32_t)(r * 272 + kg * 16);
            *(uint4*)(smem + SM_BHI + off) =
                *(const uint4*)((const char*)g_WThi + ((size_t)(bn + r) * Cc + kg * 8) * 2);
            *(uint4*)(smem + SM_BLO + off) =
                *(const uint4*)((const char*)g_WTlo + ((size_t)(bn + r) * Cc + kg * 8) * 2);
        }
        __syncthreads();

        #pragma unroll
        for (int mf = 0; mf < 4; mf++)
            #pragma unroll
            for (int nf = 0; nf < 4; nf++)
                #pragma unroll
                for (int j = 0; j < 4; j++) acc[mf][nf][j] = 0.f;

        // ---- K loop: 8 steps of k16 ----
        #pragma unroll
        for (int ks = 0; ks < 8; ks++) {
            uint32_t bh[4][2], bl[4][2];
            #pragma unroll
            for (int nf = 0; nf < 4; nf++) {
                int bo = b_base + nf * 8 * 272 + ks * 32;
                bh[nf][0] = *(const uint32_t*)(smem + SM_BHI + bo);
                bh[nf][1] = *(const uint32_t*)(smem + SM_BHI + bo + 16);
                bl[nf][0] = *(const uint32_t*)(smem + SM_BLO + bo);
                bl[nf][1] = *(const uint32_t*)(smem + SM_BLO + bo + 16);
            }
            #pragma unroll
            for (int mf = 0; mf < 4; mf++) {
                int ao = a_base + mf * 16 * 272 + ks * 32;
                uint32_t ah[4], al[4];
                ah[0] = *(const uint32_t*)(smem + SM_AHI + ao);
                ah[1] = *(const uint32_t*)(smem + SM_AHI + ao + 2176);
                ah[2] = *(const uint32_t*)(smem + SM_AHI + ao + 16);
                ah[3] = *(const uint32_t*)(smem + SM_AHI + ao + 2176 + 16);
                al[0] = *(const uint32_t*)(smem + SM_ALO + ao);
                al[1] = *(const uint32_t*)(smem + SM_ALO + ao + 2176);
                al[2] = *(const uint32_t*)(smem + SM_ALO + ao + 16);
                al[3] = *(const uint32_t*)(smem + SM_ALO + ao + 2176 + 16);
                #pragma unroll
                for (int nf = 0; nf < 4; nf++) {
                    mma16816(acc[mf][nf], ah, bh[nf]);
                    mma16816(acc[mf][nf], ah, bl[nf]);
                    mma16816(acc[mf][nf], al, bh[nf]);
                }
            }
        }

        // ---- epilogue: write h (fp16), accumulate attention dots (fp32) ----
        #pragma unroll
        for (int mf = 0; mf < 4; mf++) {
            #pragma unroll
            for (int i = 0; i < 2; i++) {
                int row = wm * 64 + mf * 16 + i * 8 + g;
                int gm  = bm + row;
                float as_p = 0.f, ad_p = 0.f;
                #pragma unroll
                for (int nf = 0; nf < 4; nf++) {
                    float c0 = acc[mf][nf][i * 2];
                    float c1 = acc[mf][nf][i * 2 + 1];
                    int col = nt * 128 + wn * 32 + nf * 8 + q * 2;
                    if (gm < Nn)
                        *(__half2*)(g_h + (size_t)gm * Ff + col) = __floats2half2_rn(c0, c1);
                    as_p += c0 * s_atts[col] + c1 * s_atts[col + 1];
                    ad_p += c0 * s_attd[col] + c1 * s_attd[col + 1];
                }
                as_p += __shfl_xor_sync(0xffffffffu, as_p, 1);
                as_p += __shfl_xor_sync(0xffffffffu, as_p, 2);
                ad_p += __shfl_xor_sync(0xffffffffu, ad_p, 1);
                ad_p += __shfl_xor_sync(0xffffffffu, ad_p, 2);
                if (q == 0) {
                    atomicAdd(&s_as[row * 2 + ht], as_p);   // head == nt
                    atomicAdd(&s_ad[row * 2 + ht], ad_p);
                }
            }
        }
        __syncthreads();
    }

    // ---- write attention coefficients (this CTA's 2 heads only) ----
    if (tid < 256) {
        int row = tid >> 1, hh = tid & 1;
        int gm = bm + row;
        if (gm < Nn) {
            g_as[gm * 4 + half * 2 + hh] = s_as[tid];
            g_ad[gm * 4 + half * 2 + hh] = s_ad[tid];
        }
    }
}

// ---------------- edge phase: single-pass softmax + aggregate + update ---
__global__ __launch_bounds__(128) void edge_kernel(const float* __restrict__ bias,
                                                   float* __restrict__ Xall,
                                                   float* __restrict__ Yall, int l)
{
    const int d = blockIdx.x;
    const int tid = threadIdx.x;
    const int lane = tid & 31, wp = tid >> 5;
    const int r0 = g_rowptr[d];
    const int deg = g_rowptr[d + 1] - r0;
    const float4 ad = *(const float4*)(g_ad + d * 4);

    __shared__ float4 red[4];
    __shared__ int    s_s[128];
    __shared__ float4 s_w[128];

    float4 acc = make_float4(0.f, 0.f, 0.f, 0.f);
    float4 den = make_float4(0.f, 0.f, 0.f, 0.f);

    for (int base = 0; base < deg; base += 128) {
        int cnt = min(128, deg - base);
        if (tid < cnt) {
            int s = g_col[r0 + base + tid];
            float4 as = *(const float4*)(g_as + s * 4);
            float e0 = as.x + ad.x; e0 = fmaxf(e0, 0.2f * e0);
            float e1 = as.y + ad.y; e1 = fmaxf(e1, 0.2f * e1);
            float e2 = as.z + ad.z; e2 = fmaxf(e2, 0.2f * e2);
            float e3 = as.w + ad.w; e3 = fmaxf(e3, 0.2f * e3);
            float w0 = expf(e0), w1 = expf(e1);
            float w2 = expf(e2), w3 = expf(e3);
            s_s[tid] = s;
            s_w[tid] = make_float4(w0, w1, w2, w3);
            den.x += w0; den.y += w1; den.z += w2; den.w += w3;
        }
        __syncthreads();
        const float* wf = (const float*)s_w;
        #pragma unroll 4
        for (int i = 0; i < cnt; i++) {
            float w = wf[i * 4 + wp];
            uint2 u = *(const uint2*)(g_h + (size_t)s_s[i] * Ff + tid * 4);
            float2 f0 = __half22float2(*(const __half2*)&u.x);
            float2 f1 = __half22float2(*(const __half2*)&u.y);
            acc.x = fmaf(w, f0.x, acc.x);
            acc.y = fmaf(w, f0.y, acc.y);
            acc.z = fmaf(w, f1.x, acc.z);
            acc.w = fmaf(w, f1.y, acc.w);
        }
        __syncthreads();
    }

    // block-reduce denominator (per head)
    #pragma unroll
    for (int o = 16; o; o >>= 1) {
        den.x += __shfl_xor_sync(0xffffffffu, den.x, o);
        den.y += __shfl_xor_sync(0xffffffffu, den.y, o);
        den.z += __shfl_xor_sync(0xffffffffu, den.z, o);
        den.w += __shfl_xor_sync(0xffffffffu, den.w, o);
    }
    if (lane == 0) red[wp] = den;
    __syncthreads();
    float4 D;
    D.x = red[0].x + red[1].x + red[2].x + red[3].x;
    D.y = red[0].y + red[1].y + red[2].y + red[3].y;
    D.z = red[0].z + red[1].z + red[2].z + red[3].z;
    D.w = red[0].w + red[1].w + red[2].w + red[3].w;
    float dh = (wp == 0) ? D.x : (wp == 1) ? D.y : (wp == 2) ? D.z : D.w;
    float R = 1.0f / dh;

    // + bias, ELU, regroup-mean (flat 4t..4t+3 -> agg[t]), GraphCON update
    float4 b = *(const float4*)(bias + tid * 4);
    float v0 = acc.x * R + b.x; v0 = v0 > 0.f ? v0 : expm1f(v0);
    float v1 = acc.y * R + b.y; v1 = v1 > 0.f ? v1 : expm1f(v1);
    float v2 = acc.z * R + b.z; v2 = v2 > 0.f ? v2 : expm1f(v2);
    float v3 = acc.w * R + b.w; v3 = v3 > 0.f ? v3 : expm1f(v3);
    float agg = 0.25f * (v0 + v1 + v2 + v3);

    size_t ofs = (size_t)d * XSTR + (size_t)l * Cc + tid;
    float xold = Xall[ofs];
    Xall[ofs + Cc] = agg;            // X_{l+1} = agg
    Yall[ofs + Cc] = agg - xold;     // Y_{l+1} = agg - X_l
}

// ---------------- classifier: out = X4 @ Wr^T + br -----------------------
__global__ __launch_bounds__(64) void logits_kernel(const float* __restrict__ Xall,
                                                    const float* __restrict__ Wr,
                                                    const float* __restrict__ br,
                                                    float* __restrict__ out)
{
    __shared__ float Xs[32 * 132];
    __shared__ float Ws[40 * 132];
    __shared__ float bs[40];
    const int tid = threadIdx.x;
    const int bmn = blockIdx.x * 32;

    for (int f = tid; f < 32 * 32; f += 64) {
        int r = f >> 5, k4 = (f & 31) << 2;
        int g = bmn + r;
        float4 v = make_float4(0.f, 0.f, 0.f, 0.f);
        if (g < Nn) v = *(const float4*)(Xall + (size_t)g * XSTR + 4 * Cc + k4);
        *(float4*)(Xs + r * 132 + k4) = v;
    }
    for (int f = tid; f < 40 * 32; f += 64) {
        int r = f >> 5, k4 = (f & 31) << 2;
        *(float4*)(Ws + r * 132 + k4) = *(const float4*)(Wr + (size_t)r * Cc + k4);
    }
    if (tid < 40) bs[tid] = br[tid];
    __syncthreads();

    const int ty = tid >> 3, tx = tid & 7;
    float acc[4][5];
    #pragma unroll
    for (int i = 0; i < 4; i++)
        #pragma unroll
        for (int j = 0; j < 5; j++) acc[i][j] = 0.f;

    #pragma unroll 4
    for (int k = 0; k < 128; k++) {
        float a[4], b[5];
        #pragma unroll
        for (int i = 0; i < 4; i++) a[i] = Xs[(ty * 4 + i) * 132 + k];
        #pragma unroll
        for (int j = 0; j < 5; j++) b[j] = Ws[(tx * 5 + j) * 132 + k];
        #pragma unroll
        for (int i = 0; i < 4; i++)
            #pragma unroll
            for (int j = 0; j < 5; j++) acc[i][j] = fmaf(a[i], b[j], acc[i][j]);
    }
    #pragma unroll
    for (int i = 0; i < 4; i++) {
        int g = bmn + ty * 4 + i;
        if (g < Nn)
            #pragma unroll
            for (int j = 0; j < 5; j++)
                out[(size_t)g * NCLS + tx * 5 + j] = acc[i][j] + bs[tx * 5 + j];
    }
}

// ---------------- launch --------------------------------------------------
extern "C" void kernel_launch(void* const* d_in, const int* in_sizes, int n_in,
                              void* d_out, int out_size)
{
    const float* x     = (const float*)d_in[0];
    const int*   src   = (const int*)  d_in[1];
    const int*   dst   = (const int*)  d_in[2];
    const float* W     = (const float*)d_in[3];
    const float* att_s = (const float*)d_in[4];
    const float* att_d = (const float*)d_in[5];
    const float* bias  = (const float*)d_in[6];
    const float* Wr    = (const float*)d_in[7];
    const float* br    = (const float*)d_in[8];

    float* out  = (float*)d_out;
    float* Xall = out + (size_t)Nn * NCLS;            // [N, 5, 128]
    float* Yall = Xall + (size_t)Nn * 5 * Cc;         // [N, 5, 128]

    cudaFuncSetAttribute(mma_gemm_kernel, cudaFuncAttributeMaxDynamicSharedMemorySize,
                         SMEM_MG);
    cudaFuncSetAttribute(scan_kernel, cudaFuncAttributeMaxDynamicSharedMemorySize,
                         SCAN_SMEM);

    init_kernel<<<(Nn * Cc + 255) / 256, 256>>>(x, Xall, Yall);
    split_w_kernel<<<(Cc * Ff + 255) / 256, 256>>>(W);
    count_kernel<<<(ET + 255) / 256, 256>>>(dst);
    scan_kernel<<<1, 1024, SCAN_SMEM>>>();
    fill_kernel<<<(ET + 255) / 256, 256>>>(src, dst);

    for (int l = 0; l < 4; l++) {
        mma_gemm_kernel<<<dim3(157, 2), 256, SMEM_MG>>>(Xall, l * Cc, att_s, att_d);
        edge_kernel<<<Nn, 128>>>(bias, Xall, Yall, l);
    }
    logits_kernel<<<(Nn + 31) / 32, 64>>>(Xall, Wr, br, out);
}